// round 13
// baseline (speedup 1.0000x reference)
#include <cuda_runtime.h>
#include <cuda_bf16.h>
#include <math.h>
#include <stdint.h>

// Problem constants (fixed by the dataset)
#define NNODES 100000
#define NEDGES 1600000
#define DIN 128
#define DH  128
#define DOUT 64

// ---------------- device scratch (no allocations; zero-init at module load) ----------------
__device__ __align__(16) static uint32_t g_featbf[(size_t)NNODES * 64]; // features*norm_src, bf16 pairs
__device__ __align__(16) static uint32_t g_h[(size_t)NNODES * 64];      // h1 layer output
__device__ __align__(16) static uint32_t g_G[(size_t)NNODES * 32];      // h2 @ W3 (64 cols)
__device__ static int   g_rowptr[NNODES + 1];
__device__ static int   g_cursor[NNODES + 1];
__device__ __align__(16) static int g_colidx[NEDGES];
__device__ static int   g_outdeg[NNODES];                               // re-zeroed by scatter
__device__ static int   g_indeg[NNODES];                                // re-zeroed by scatter
__device__ static float g_norm_src[NNODES];
__device__ static float g_norm_dst[NNODES];
__device__ static volatile unsigned long long g_state[128];             // lookback state, re-zeroed by scatter

// ---------------- helpers ----------------
__device__ __forceinline__ uint32_t pack_bf16(float lo, float hi) {
    uint32_t r; asm("cvt.rn.bf16x2.f32 %0, %1, %2;" : "=r"(r) : "f"(hi), "f"(lo)); return r;
}
// accumulate a bf16x2 word into an f32x2 accumulator: SHL + LOP3 + ADD2 (exact)
__device__ __forceinline__ void acc_bf16x2(unsigned long long& acc, uint32_t w) {
    unsigned long long val;
    asm("{\n\t.reg .b32 lo, hi;\n\t"
        "shl.b32 lo, %1, 16;\n\t"
        "and.b32 hi, %1, 0xFFFF0000;\n\t"
        "mov.b64 %0, {lo, hi};\n\t}"
        : "=l"(val) : "r"(w));
    asm("add.rn.f32x2 %0, %0, %1;" : "+l"(acc) : "l"(val));
}
__device__ __forceinline__ void add_f32x2(unsigned long long& a, unsigned long long b) {
    asm("add.rn.f32x2 %0, %0, %1;" : "+l"(a) : "l"(b));
}
__device__ __forceinline__ float2 unpack_f32x2(unsigned long long a) {
    uint32_t lo, hi;
    asm("mov.b64 {%0, %1}, %2;" : "=r"(lo), "=r"(hi) : "l"(a));
    return make_float2(__uint_as_float(lo), __uint_as_float(hi));
}

// ---------------- kernel 1: degree histogram (4 edges/thread, int4 loads) ----------------
__global__ __launch_bounds__(256) void deg_kernel(
    const int4* __restrict__ src4, const int4* __restrict__ dst4, int E4, int E)
{
    int i = blockIdx.x * 256 + threadIdx.x;
    if (i < E4) {
        int4 s = __ldg(&src4[i]);
        int4 d = __ldg(&dst4[i]);
        atomicAdd(&g_outdeg[s.x], 1); atomicAdd(&g_outdeg[s.y], 1);
        atomicAdd(&g_outdeg[s.z], 1); atomicAdd(&g_outdeg[s.w], 1);
        atomicAdd(&g_indeg[d.x], 1);  atomicAdd(&g_indeg[d.y], 1);
        atomicAdd(&g_indeg[d.z], 1);  atomicAdd(&g_indeg[d.w], 1);
    }
    if (i == 0) {  // tail (E not multiple of 4)
        const int* src = (const int*)src4;
        const int* dst = (const int*)dst4;
        for (int e = E4 * 4; e < E; e++) {
            atomicAdd(&g_outdeg[src[e]], 1);
            atomicAdd(&g_indeg[dst[e]], 1);
        }
    }
}

// ---------------- kernel 2: single-pass scan (decoupled lookback) + norms ----------------
// grid = ceil(N/1024) = 98 blocks (< 148 SMs -> all co-resident, no deadlock)
__global__ __launch_bounds__(256) void scan_kernel(int n, int E)
{
    __shared__ int warp_sums[8];
    __shared__ int s_prefix;
    int b = blockIdx.x, t = threadIdx.x;
    int lane = t & 31, wid = t >> 5;
    int idx0 = b * 1024 + t * 4;

    int v[4];
#pragma unroll
    for (int i = 0; i < 4; i++) { int idx = idx0 + i; v[i] = (idx < n) ? g_indeg[idx] : 0; }
    int s = v[0] + v[1] + v[2] + v[3];
    int ss = s;
#pragma unroll
    for (int o = 1; o < 32; o <<= 1) { int x = __shfl_up_sync(0xFFFFFFFFu, ss, o); if (lane >= o) ss += x; }
    if (lane == 31) warp_sums[wid] = ss;
    __syncthreads();
    if (wid == 0) {
        int w = (lane < 8) ? warp_sums[lane] : 0;
#pragma unroll
        for (int o = 1; o < 8; o <<= 1) { int x = __shfl_up_sync(0xFFFFFFFFu, w, o); if (lane >= o) w += x; }
        if (lane < 8) warp_sums[lane] = w;
    }
    __syncthreads();
    int T = warp_sums[7];
    int excl_in_block = ss - s + ((wid > 0) ? warp_sums[wid - 1] : 0);

    if (t == 0) {
        unsigned long long pk = ((unsigned long long)(unsigned)T << 2) | (b == 0 ? 2u : 1u);
        g_state[b] = pk;
        __threadfence();
    }
    if (wid == 0) {
        int running = 0;
        if (b > 0) {
            int look = b - 1 - lane;
            while (true) {
                unsigned long long sv = (look >= 0) ? g_state[look] : 2ULL;
                unsigned flag = (unsigned)(sv & 3ULL);
                int val = (int)(sv >> 2);
                unsigned inv = __ballot_sync(0xFFFFFFFFu, flag == 0u);
                if (inv) continue;
                unsigned pref = __ballot_sync(0xFFFFFFFFu, flag == 2u);
                if (pref) {
                    int fp = __ffs(pref) - 1;
                    int contrib = (lane <= fp) ? val : 0;
#pragma unroll
                    for (int o = 16; o > 0; o >>= 1) contrib += __shfl_xor_sync(0xFFFFFFFFu, contrib, o);
                    running += contrib;
                    break;
                } else {
                    int contrib = val;
#pragma unroll
                    for (int o = 16; o > 0; o >>= 1) contrib += __shfl_xor_sync(0xFFFFFFFFu, contrib, o);
                    running += contrib;
                    look -= 32;
                }
            }
        }
        if (t == 0) {
            s_prefix = running;
            if (b > 0) {
                unsigned long long pk = ((unsigned long long)(unsigned)(running + T) << 2) | 2u;
                g_state[b] = pk;
                __threadfence();
            }
        }
    }
    __syncthreads();

    int run = s_prefix + excl_in_block;
#pragma unroll
    for (int i = 0; i < 4; i++) {
        int idx = idx0 + i;
        if (idx < n) {
            g_rowptr[idx] = run;
            g_cursor[idx] = run;
            int od = g_outdeg[idx]; if (od < 1) od = 1;
            int id = v[i];          if (id < 1) id = 1;
            g_norm_src[idx] = rsqrtf((float)od);
            g_norm_dst[idx] = rsqrtf((float)id);
        }
        run += v[i];
    }
    if (b == 0 && t == 0) g_rowptr[n] = E;
}

// ---------------- kernel 3: scatter + convert, DISJOINT thread ranges (R12 proven) ----------------
__global__ __launch_bounds__(256) void scatter_convert_kernel(
    const int4* __restrict__ src4, const int4* __restrict__ dst4,
    const float4* __restrict__ feat4, int E4, int E, int n, int nconv)
{
    int i = blockIdx.x * 256 + threadIdx.x;
    if (i < E4) {
        int4 s = __ldg(&src4[i]);
        int4 d = __ldg(&dst4[i]);
        g_colidx[atomicAdd(&g_cursor[d.x], 1)] = s.x;
        g_colidx[atomicAdd(&g_cursor[d.y], 1)] = s.y;
        g_colidx[atomicAdd(&g_cursor[d.z], 1)] = s.z;
        g_colidx[atomicAdd(&g_cursor[d.w], 1)] = s.w;
        if (i == 0) {  // tail
            const int* src = (const int*)src4;
            const int* dst = (const int*)dst4;
            for (int e = E4 * 4; e < E; e++) {
                g_colidx[atomicAdd(&g_cursor[dst[e]], 1)] = src[e];
            }
        }
    } else {
        int q = i - E4;                 // uint4 index into g_featbf
        if (q < nconv) {
            int node = q >> 4;          // 16 uint4s per node row
            float ns = __ldg(&g_norm_src[node]);
            float4 f0 = __ldg(&feat4[(size_t)q * 2]);
            float4 f1 = __ldg(&feat4[(size_t)q * 2 + 1]);
            uint4 o;
            o.x = pack_bf16(f0.x * ns, f0.y * ns); o.y = pack_bf16(f0.z * ns, f0.w * ns);
            o.z = pack_bf16(f1.x * ns, f1.y * ns); o.w = pack_bf16(f1.z * ns, f1.w * ns);
            ((uint4*)g_featbf)[q] = o;
        }
    }
    if (i < n) { g_outdeg[i] = 0; g_indeg[i] = 0; }   // consumed by scan; reset for next call
    if (i < 128) g_state[i] = 0ULL;
}

// ---------------- bf16 tensor-core GEMM pieces ----------------
#define AS_STRIDE 68
#define BSS128 136
#define W3S_STRIDE 72
__device__ __forceinline__ void mma_bf16(float* d, const uint32_t* a, const uint32_t* b) {
    asm volatile(
        "mma.sync.aligned.m16n8k16.row.col.f32.bf16.bf16.f32 "
        "{%0,%1,%2,%3}, {%4,%5,%6,%7}, {%8,%9}, {%0,%1,%2,%3};\n"
        : "+f"(d[0]), "+f"(d[1]), "+f"(d[2]), "+f"(d[3])
        : "r"(a[0]), "r"(a[1]), "r"(a[2]), "r"(a[3]), "r"(b[0]), "r"(b[1]));
}

// ---- in-kernel aggregation: warp wid aggregates rows [wid*16, wid*16+16) of this block's
// 128-node tile directly into As smem (bf16 pairs, MMA layout). Occupancy is smem-capped in
// the GEMM kernels, so the deep-MLP (8 gathers in flight) register cost here is free.
__device__ __forceinline__ void agg_tile_to_smem(
    const uint2* __restrict__ x, uint32_t* As, int m0, int wid, int lane, int M)
{
    const uint2* xp = x + lane;
    for (int k = 0; k < 16; k++) {
        int row = wid * 16 + k;
        int node = m0 + row;
        unsigned long long a0 = 0ULL, a1 = 0ULL, b0 = 0ULL, b1 = 0ULL;
        unsigned long long c0 = 0ULL, c1 = 0ULL, d0 = 0ULL, d1 = 0ULL;
        float dsc = 0.f;
        if (node < M) {
            int beg = __ldg(&g_rowptr[node]);
            int end = __ldg(&g_rowptr[node + 1]);
            dsc = __ldg(&g_norm_dst[node]);
            int e = beg;
            for (; e + 7 < end; e += 8) {
                int u0 = __ldg(&g_colidx[e]);
                int u1 = __ldg(&g_colidx[e + 1]);
                int u2 = __ldg(&g_colidx[e + 2]);
                int u3 = __ldg(&g_colidx[e + 3]);
                int u4 = __ldg(&g_colidx[e + 4]);
                int u5 = __ldg(&g_colidx[e + 5]);
                int u6 = __ldg(&g_colidx[e + 6]);
                int u7 = __ldg(&g_colidx[e + 7]);
                uint2 v0 = __ldg(xp + (size_t)u0 * 32);
                uint2 v1 = __ldg(xp + (size_t)u1 * 32);
                uint2 v2 = __ldg(xp + (size_t)u2 * 32);
                uint2 v3 = __ldg(xp + (size_t)u3 * 32);
                uint2 v4 = __ldg(xp + (size_t)u4 * 32);
                uint2 v5 = __ldg(xp + (size_t)u5 * 32);
                uint2 v6 = __ldg(xp + (size_t)u6 * 32);
                uint2 v7 = __ldg(xp + (size_t)u7 * 32);
                acc_bf16x2(a0, v0.x); acc_bf16x2(a1, v0.y);
                acc_bf16x2(b0, v1.x); acc_bf16x2(b1, v1.y);
                acc_bf16x2(c0, v2.x); acc_bf16x2(c1, v2.y);
                acc_bf16x2(d0, v3.x); acc_bf16x2(d1, v3.y);
                acc_bf16x2(a0, v4.x); acc_bf16x2(a1, v4.y);
                acc_bf16x2(b0, v5.x); acc_bf16x2(b1, v5.y);
                acc_bf16x2(c0, v6.x); acc_bf16x2(c1, v6.y);
                acc_bf16x2(d0, v7.x); acc_bf16x2(d1, v7.y);
            }
            for (; e + 1 < end; e += 2) {
                int u0 = __ldg(&g_colidx[e]);
                int u1 = __ldg(&g_colidx[e + 1]);
                uint2 v0 = __ldg(xp + (size_t)u0 * 32);
                uint2 v1 = __ldg(xp + (size_t)u1 * 32);
                acc_bf16x2(a0, v0.x); acc_bf16x2(a1, v0.y);
                acc_bf16x2(b0, v1.x); acc_bf16x2(b1, v1.y);
            }
            if (e < end) {
                int u0 = __ldg(&g_colidx[e]);
                uint2 v0 = __ldg(xp + (size_t)u0 * 32);
                acc_bf16x2(c0, v0.x); acc_bf16x2(c1, v0.y);
            }
        }
        add_f32x2(a0, b0); add_f32x2(c0, d0); add_f32x2(a0, c0);
        add_f32x2(a1, b1); add_f32x2(c1, d1); add_f32x2(a1, c1);
        float2 f0 = unpack_f32x2(a0);
        float2 f1 = unpack_f32x2(a1);
        uint2 r;
        r.x = pack_bf16(f0.x * dsc, f0.y * dsc);
        r.y = pack_bf16(f1.x * dsc, f1.y * dsc);
        *(uint2*)&As[row * AS_STRIDE + 2 * lane] = r;   // STS.64, contiguous, conflict-free
    }
}

// ---- fused layer 1: As = aggregate(featbf); h1 = relu(As@W1 + b1) * ns (bf16 out) ----
__global__ __launch_bounds__(256) void agg_gemm_l1_kernel(
    const uint2* __restrict__ x,      // featbf
    const float* __restrict__ W, const float* __restrict__ bias,
    const float* __restrict__ rowscale,
    uint32_t* __restrict__ C, int M)
{
    extern __shared__ uint32_t smem_u[];
    uint32_t* As = smem_u;                    // [128][68]
    uint32_t* Bs = smem_u + 128 * AS_STRIDE;  // [64][136]

    const int t    = threadIdx.x;
    const int lane = t & 31;
    const int wid  = t >> 5;
    const int m0   = blockIdx.x * 128;
    const int g    = lane >> 2;
    const int tt   = lane & 3;
    const int wm   = wid & 3;
    const int wn   = wid >> 2;

    // stage W1 -> Bs
    for (int i = t; i < 64 * 32; i += 256) {
        int kk = i >> 5;
        int n4 = (i & 31) * 4;
        float4 r0 = __ldg((const float4*)&W[(size_t)(2 * kk) * 128 + n4]);
        float4 r1 = __ldg((const float4*)&W[(size_t)(2 * kk + 1) * 128 + n4]);
        uint4 o;
        o.x = pack_bf16(r0.x, r1.x); o.y = pack_bf16(r0.y, r1.y);
        o.z = pack_bf16(r0.z, r1.z); o.w = pack_bf16(r0.w, r1.w);
        *(uint4*)&Bs[kk * BSS128 + n4] = o;
    }
    // aggregate this block's 128 nodes into As
    agg_tile_to_smem(x, As, m0, wid, lane, M);
    __syncthreads();

    float acc[2][8][4];
#pragma unroll
    for (int i = 0; i < 2; i++)
#pragma unroll
        for (int j = 0; j < 8; j++)
#pragma unroll
            for (int c = 0; c < 4; c++) acc[i][j][c] = 0.f;

#pragma unroll
    for (int ks = 0; ks < 8; ks++) {
        int kb = ks * 8;
        uint32_t bf[8][2];
#pragma unroll
        for (int j = 0; j < 8; j++) {
            int n = wn * 64 + j * 8 + g;
            bf[j][0] = Bs[(kb + tt) * BSS128 + n];
            bf[j][1] = Bs[(kb + tt + 4) * BSS128 + n];
        }
#pragma unroll
        for (int i = 0; i < 2; i++) {
            int m = wm * 32 + i * 16;
            uint32_t af[4];
            af[0] = As[(m + g)     * AS_STRIDE + kb + tt];
            af[1] = As[(m + g + 8) * AS_STRIDE + kb + tt];
            af[2] = As[(m + g)     * AS_STRIDE + kb + tt + 4];
            af[3] = As[(m + g + 8) * AS_STRIDE + kb + tt + 4];
#pragma unroll
            for (int j = 0; j < 8; j++) mma_bf16(acc[i][j], af, bf[j]);
        }
    }

#pragma unroll
    for (int i = 0; i < 2; i++) {
        int m_lo = m0 + wm * 32 + i * 16 + g;
        int m_hi = m_lo + 8;
        float rs_lo = 1.f, rs_hi = 1.f;
        if (m_lo < M) rs_lo = __ldg(&rowscale[m_lo]);
        if (m_hi < M) rs_hi = __ldg(&rowscale[m_hi]);
#pragma unroll
        for (int j = 0; j < 8; j++) {
            int n = wn * 64 + j * 8 + 2 * tt;
            float b0 = __ldg(&bias[n]), b1 = __ldg(&bias[n + 1]);
            float v0 = fmaxf(acc[i][j][0] + b0, 0.f) * rs_lo;
            float v1 = fmaxf(acc[i][j][1] + b1, 0.f) * rs_lo;
            float v2 = fmaxf(acc[i][j][2] + b0, 0.f) * rs_hi;
            float v3 = fmaxf(acc[i][j][3] + b1, 0.f) * rs_hi;
            if (m_lo < M) C[(size_t)m_lo * 64 + (n >> 1)] = pack_bf16(v0, v1);
            if (m_hi < M) C[(size_t)m_hi * 64 + (n >> 1)] = pack_bf16(v2, v3);
        }
    }
}

// ---- fused layers 2+3: As = aggregate(h1); h2 = relu(As@W2+b2)*ns (kept in smem);
//      G = h2 @ W3 (bf16 out, 64 cols) ----
__global__ __launch_bounds__(256) void agg_gemm_fused_kernel(
    const uint2* __restrict__ x,      // h1
    const float* __restrict__ W2, const float* __restrict__ bias,
    const float* __restrict__ rowscale,
    const float* __restrict__ W3,
    uint32_t* __restrict__ C, int M)
{
    extern __shared__ uint32_t smem_u[];
    uint32_t* As  = smem_u;                           // [128][68]  (m2, then h2)
    uint32_t* Bs  = smem_u + 128 * AS_STRIDE;         // [64][136]  (W2)
    uint32_t* W3s = Bs + 64 * BSS128;                 // [64][72]   (W3)

    const int t    = threadIdx.x;
    const int lane = t & 31;
    const int wid  = t >> 5;
    const int m0   = blockIdx.x * 128;
    const int g    = lane >> 2;
    const int tt   = lane & 3;
    const int wm   = wid & 3;
    const int wn   = wid >> 2;

    for (int i = t; i < 64 * 32; i += 256) {
        int kk = i >> 5;
        int n4 = (i & 31) * 4;
        float4 r0 = __ldg((const float4*)&W2[(size_t)(2 * kk) * 128 + n4]);
        float4 r1 = __ldg((const float4*)&W2[(size_t)(2 * kk + 1) * 128 + n4]);
        uint4 o;
        o.x = pack_bf16(r0.x, r1.x); o.y = pack_bf16(r0.y, r1.y);
        o.z = pack_bf16(r0.z, r1.z); o.w = pack_bf16(r0.w, r1.w);
        *(uint4*)&Bs[kk * BSS128 + n4] = o;
    }
    for (int i = t; i < 64 * 16; i += 256) {
        int kk = i >> 4;
        int n4 = (i & 15) * 4;
        float4 r0 = __ldg((const float4*)&W3[(size_t)(2 * kk) * 64 + n4]);
        float4 r1 = __ldg((const float4*)&W3[(size_t)(2 * kk + 1) * 64 + n4]);
        uint4 o;
        o.x = pack_bf16(r0.x, r1.x); o.y = pack_bf16(r0.y, r1.y);
        o.z = pack_bf16(r0.z, r1.z); o.w = pack_bf16(r0.w, r1.w);
        *(uint4*)&W3s[kk * W3S_STRIDE + n4] = o;
    }
    // aggregate this block's 128 nodes (from h1) into As
    agg_tile_to_smem(x, As, m0, wid, lane, M);
    __syncthreads();

    // ---- mainloop 1: acc = m2 @ W2 ----
    float acc[2][8][4];
#pragma unroll
    for (int i = 0; i < 2; i++)
#pragma unroll
        for (int j = 0; j < 8; j++)
#pragma unroll
            for (int c = 0; c < 4; c++) acc[i][j][c] = 0.f;

#pragma unroll
    for (int ks = 0; ks < 8; ks++) {
        int kb = ks * 8;
        uint32_t bf[8][2];
#pragma unroll
        for (int j = 0; j < 8; j++) {
            int n = wn * 64 + j * 8 + g;
            bf[j][0] = Bs[(kb + tt) * BSS128 + n];
            bf[j][1] = Bs[(kb + tt + 4) * BSS128 + n];
        }
#pragma unroll
        for (int i = 0; i < 2; i++) {
            int m = wm * 32 + i * 16;
            uint32_t af[4];
            af[0] = As[(m + g)     * AS_STRIDE + kb + tt];
            af[1] = As[(m + g + 8) * AS_STRIDE + kb + tt];
            af[2] = As[(m + g)     * AS_STRIDE + kb + tt + 4];
            af[3] = As[(m + g + 8) * AS_STRIDE + kb + tt + 4];
#pragma unroll
            for (int j = 0; j < 8; j++) mma_bf16(acc[i][j], af, bf[j]);
        }
    }
    __syncthreads();   // all warps done reading As (m2) before overwriting with h2

    // ---- epilogue 1: h2 = relu(acc + b2) * ns  ->  As smem ----
#pragma unroll
    for (int i = 0; i < 2; i++) {
        int row_lo = wm * 32 + i * 16 + g;
        int m_lo = m0 + row_lo;
        int m_hi = m_lo + 8;
        float rs_lo = 1.f, rs_hi = 1.f;
        if (m_lo < M) rs_lo = __ldg(&rowscale[m_lo]);
        if (m_hi < M) rs_hi = __ldg(&rowscale[m_hi]);
#pragma unroll
        for (int j = 0; j < 8; j++) {
            int n = wn * 64 + j * 8 + 2 * tt;
            float b0 = __ldg(&bias[n]), b1 = __ldg(&bias[n + 1]);
            float v0 = fmaxf(acc[i][j][0] + b0, 0.f) * rs_lo;
            float v1 = fmaxf(acc[i][j][1] + b1, 0.f) * rs_lo;
            float v2 = fmaxf(acc[i][j][2] + b0, 0.f) * rs_hi;
            float v3 = fmaxf(acc[i][j][3] + b1, 0.f) * rs_hi;
            int colp = n >> 1;
            As[row_lo * AS_STRIDE + colp]       = pack_bf16(v0, v1);
            As[(row_lo + 8) * AS_STRIDE + colp] = pack_bf16(v2, v3);
        }
    }
    __syncthreads();

    // ---- mainloop 2: acc2 = h2 @ W3 ----
    float acc2[2][4][4];
#pragma unroll
    for (int i = 0; i < 2; i++)
#pragma unroll
        for (int j = 0; j < 4; j++)
#pragma unroll
            for (int c = 0; c < 4; c++) acc2[i][j][c] = 0.f;

#pragma unroll
    for (int ks = 0; ks < 8; ks++) {
        int kb = ks * 8;
        uint32_t bf[4][2];
#pragma unroll
        for (int j = 0; j < 4; j++) {
            int n = wn * 32 + j * 8 + g;
            bf[j][0] = W3s[(kb + tt) * W3S_STRIDE + n];
            bf[j][1] = W3s[(kb + tt + 4) * W3S_STRIDE + n];
        }
#pragma unroll
        for (int i = 0; i < 2; i++) {
            int m = wm * 32 + i * 16;
            uint32_t af[4];
            af[0] = As[(m + g)     * AS_STRIDE + kb + tt];
            af[1] = As[(m + g + 8) * AS_STRIDE + kb + tt];
            af[2] = As[(m + g)     * AS_STRIDE + kb + tt + 4];
            af[3] = As[(m + g + 8) * AS_STRIDE + kb + tt + 4];
#pragma unroll
            for (int j = 0; j < 4; j++) mma_bf16(acc2[i][j], af, bf[j]);
        }
    }

#pragma unroll
    for (int i = 0; i < 2; i++) {
        int m_lo = m0 + wm * 32 + i * 16 + g;
        int m_hi = m_lo + 8;
#pragma unroll
        for (int j = 0; j < 4; j++) {
            int n = wn * 32 + j * 8 + 2 * tt;
            if (m_lo < M) C[(size_t)m_lo * 32 + (n >> 1)] = pack_bf16(acc2[i][j][0], acc2[i][j][1]);
            if (m_hi < M) C[(size_t)m_hi * 32 + (n >> 1)] = pack_bf16(acc2[i][j][2], acc2[i][j][3]);
        }
    }
}

// ---------------- SpMM over G (64 cols) fused with +b3 and log_softmax ----------------
__global__ __launch_bounds__(256) void spmm_final_kernel(
    const uint32_t* __restrict__ G, const float* __restrict__ b3,
    float* __restrict__ out, int n)
{
    int warp = (blockIdx.x * 256 + threadIdx.x) >> 5;
    int lane = threadIdx.x & 31;
    if (warp >= n) return;
    int beg = __ldg(&g_rowptr[warp]);
    int end = __ldg(&g_rowptr[warp + 1]);
    float dsc = __ldg(&g_norm_dst[warp]);
    const uint32_t* gp = G + lane;

    unsigned long long a0 = 0ULL, b0 = 0ULL;
    int e = beg;
    for (; e < end && (e & 3); e++) {
        int u = __ldg(&g_colidx[e]);
        acc_bf16x2(b0, __ldg(gp + (size_t)u * 32));
    }
    for (; e + 3 < end; e += 4) {
        int4 u = __ldg((const int4*)&g_colidx[e]);
        uint32_t v0 = __ldg(gp + (size_t)u.x * 32);
        uint32_t v1 = __ldg(gp + (size_t)u.y * 32);
        uint32_t v2 = __ldg(gp + (size_t)u.z * 32);
        uint32_t v3 = __ldg(gp + (size_t)u.w * 32);
        acc_bf16x2(a0, v0); acc_bf16x2(b0, v1);
        acc_bf16x2(a0, v2); acc_bf16x2(b0, v3);
    }
    for (; e < end; e++) {
        int u = __ldg(&g_colidx[e]);
        acc_bf16x2(a0, __ldg(gp + (size_t)u * 32));
    }
    add_f32x2(a0, b0);
    float2 f = unpack_f32x2(a0);
    float2 bb = __ldg(&((const float2*)b3)[lane]);
    float r0 = f.x * dsc + bb.x;
    float r1 = f.y * dsc + bb.y;
    float mx = fmaxf(r0, r1);
#pragma unroll
    for (int o = 16; o > 0; o >>= 1) mx = fmaxf(mx, __shfl_xor_sync(0xFFFFFFFFu, mx, o));
    float es = __expf(r0 - mx) + __expf(r1 - mx);
#pragma unroll
    for (int o = 16; o > 0; o >>= 1) es += __shfl_xor_sync(0xFFFFFFFFu, es, o);
    float lse = logf(es) + mx;
    ((float2*)out)[(size_t)warp * 32 + lane] = make_float2(r0 - lse, r1 - lse);
}

#define GEMM_L1_SMEM    ((128 * AS_STRIDE + 64 * BSS128) * 4)
#define GEMM_FUSED_SMEM ((128 * AS_STRIDE + 64 * BSS128 + 64 * W3S_STRIDE) * 4)

// ---------------- launch ----------------
extern "C" void kernel_launch(void* const* d_in, const int* in_sizes, int n_in,
                              void* d_out, int out_size)
{
    const float* features = (const float*)d_in[0];
    const int*   src      = (const int*)  d_in[1];
    const int*   dst      = (const int*)  d_in[2];
    const float* W1       = (const float*)d_in[3];
    const float* b1       = (const float*)d_in[4];
    const float* W2       = (const float*)d_in[5];
    const float* b2       = (const float*)d_in[6];
    const float* W3       = (const float*)d_in[7];
    const float* b3       = (const float*)d_in[8];
    float* out = (float*)d_out;

    const int N = in_sizes[0] / DIN;   // 100000
    const int E = in_sizes[1];         // 1600000

    uint32_t* featbf; cudaGetSymbolAddress((void**)&featbf, g_featbf);
    uint32_t* hbuf;   cudaGetSymbolAddress((void**)&hbuf,   g_h);
    uint32_t* Gbuf;   cudaGetSymbolAddress((void**)&Gbuf,   g_G);
    float*    nsrc;   cudaGetSymbolAddress((void**)&nsrc,   g_norm_src);

    static bool attr_done = false;
    if (!attr_done) {
        cudaFuncSetAttribute((const void*)agg_gemm_l1_kernel,
                             cudaFuncAttributeMaxDynamicSharedMemorySize, GEMM_L1_SMEM);
        cudaFuncSetAttribute((const void*)agg_gemm_fused_kernel,
                             cudaFuncAttributeMaxDynamicSharedMemorySize, GEMM_FUSED_SMEM);
        attr_done = true;
    }

    const int E4 = E >> 2;
    const int nconv = N * 16;                       // one uint4 per convert thread
    const int sc_threads = E4 + nconv;              // disjoint ranges: scatter | convert
    const int scan_blocks = (N + 1023) / 1024;      // 98 < 148 SMs (lookback safety)
    const int spmm_blocks = (N * 32 + 255) / 256;   // warp per node
    const int gemm_blocks = (N + 127) / 128;

    // ---- CSR build ----
    deg_kernel<<<(E4 + 255) / 256, 256>>>((const int4*)src, (const int4*)dst, E4, E);
    scan_kernel<<<scan_blocks, 256>>>(N, E);
    scatter_convert_kernel<<<(sc_threads + 255) / 256, 256>>>(
        (const int4*)src, (const int4*)dst, (const float4*)features, E4, E, N, nconv);

    // ---- layer 1: fused aggregate + GEMM (PROFILED SLOT #4) ----
    agg_gemm_l1_kernel<<<gemm_blocks, 256, GEMM_L1_SMEM>>>(
        (const uint2*)featbf, W1, b1, nsrc, hbuf, N);

    // ---- layers 2+3: fused aggregate + GEMM(W2) + GEMM(W3) ----
    agg_gemm_fused_kernel<<<gemm_blocks, 256, GEMM_FUSED_SMEM>>>(
        (const uint2*)hbuf, W2, b2, nsrc, W3, Gbuf, N);

    // ---- layer 3 aggregate + b3 + log_softmax ----
    spmm_final_kernel<<<spmm_blocks, 256>>>(Gbuf, b3, out, N);
}

// round 14
// speedup vs baseline: 1.3009x; 1.3009x over previous
#include <cuda_runtime.h>
#include <cuda_bf16.h>
#include <math.h>
#include <stdint.h>

// Problem constants (fixed by the dataset)
#define NNODES 100000
#define NEDGES 1600000
#define DIN 128
#define DH  128
#define DOUT 64

// ---------------- device scratch (no allocations; zero-init at module load) ----------------
__device__ __align__(16) static uint32_t g_featbf[(size_t)NNODES * 64]; // features*norm_src, bf16 pairs
__device__ __align__(16) static uint32_t g_aggA[(size_t)NNODES * 64];   // aggregate buffer
__device__ __align__(16) static uint32_t g_h[(size_t)NNODES * 64];      // h1 layer output
__device__ __align__(16) static uint32_t g_G[(size_t)NNODES * 32];      // h2 @ W3 (64 cols)
__device__ static int   g_rowptr[NNODES + 1];
__device__ static int   g_cursor[NNODES + 1];
__device__ __align__(16) static int g_colidx[NEDGES];
__device__ static int   g_outdeg[NNODES];                               // re-zeroed by scatter
__device__ static int   g_indeg[NNODES];                                // re-zeroed by scatter
__device__ static float g_norm_src[NNODES];
__device__ static float g_norm_dst[NNODES];
__device__ static volatile unsigned long long g_state[128];             // lookback state, re-zeroed by scatter

// ---------------- helpers ----------------
__device__ __forceinline__ uint32_t pack_bf16(float lo, float hi) {
    uint32_t r; asm("cvt.rn.bf16x2.f32 %0, %1, %2;" : "=r"(r) : "f"(hi), "f"(lo)); return r;
}
// accumulate a bf16x2 word into an f32x2 accumulator: SHL + LOP3 + ADD2 (exact)
__device__ __forceinline__ void acc_bf16x2(unsigned long long& acc, uint32_t w) {
    unsigned long long val;
    asm("{\n\t.reg .b32 lo, hi;\n\t"
        "shl.b32 lo, %1, 16;\n\t"
        "and.b32 hi, %1, 0xFFFF0000;\n\t"
        "mov.b64 %0, {lo, hi};\n\t}"
        : "=l"(val) : "r"(w));
    asm("add.rn.f32x2 %0, %0, %1;" : "+l"(acc) : "l"(val));
}
__device__ __forceinline__ void add_f32x2(unsigned long long& a, unsigned long long b) {
    asm("add.rn.f32x2 %0, %0, %1;" : "+l"(a) : "l"(b));
}
__device__ __forceinline__ float2 unpack_f32x2(unsigned long long a) {
    uint32_t lo, hi;
    asm("mov.b64 {%0, %1}, %2;" : "=r"(lo), "=r"(hi) : "l"(a));
    return make_float2(__uint_as_float(lo), __uint_as_float(hi));
}

// ---------------- kernel 1: degree histogram (4 edges/thread, int4 loads) ----------------
__global__ __launch_bounds__(256) void deg_kernel(
    const int4* __restrict__ src4, const int4* __restrict__ dst4, int E4, int E)
{
    int i = blockIdx.x * 256 + threadIdx.x;
    if (i < E4) {
        int4 s = __ldg(&src4[i]);
        int4 d = __ldg(&dst4[i]);
        atomicAdd(&g_outdeg[s.x], 1); atomicAdd(&g_outdeg[s.y], 1);
        atomicAdd(&g_outdeg[s.z], 1); atomicAdd(&g_outdeg[s.w], 1);
        atomicAdd(&g_indeg[d.x], 1);  atomicAdd(&g_indeg[d.y], 1);
        atomicAdd(&g_indeg[d.z], 1);  atomicAdd(&g_indeg[d.w], 1);
    }
    if (i == 0) {  // tail (E not multiple of 4)
        const int* src = (const int*)src4;
        const int* dst = (const int*)dst4;
        for (int e = E4 * 4; e < E; e++) {
            atomicAdd(&g_outdeg[src[e]], 1);
            atomicAdd(&g_indeg[dst[e]], 1);
        }
    }
}

// ---------------- kernel 2: single-pass scan (decoupled lookback) + norms ----------------
// grid = ceil(N/1024) = 98 blocks (< 148 SMs -> all co-resident, no deadlock)
__global__ __launch_bounds__(256) void scan_kernel(int n, int E)
{
    __shared__ int warp_sums[8];
    __shared__ int s_prefix;
    int b = blockIdx.x, t = threadIdx.x;
    int lane = t & 31, wid = t >> 5;
    int idx0 = b * 1024 + t * 4;

    int v[4];
#pragma unroll
    for (int i = 0; i < 4; i++) { int idx = idx0 + i; v[i] = (idx < n) ? g_indeg[idx] : 0; }
    int s = v[0] + v[1] + v[2] + v[3];
    int ss = s;
#pragma unroll
    for (int o = 1; o < 32; o <<= 1) { int x = __shfl_up_sync(0xFFFFFFFFu, ss, o); if (lane >= o) ss += x; }
    if (lane == 31) warp_sums[wid] = ss;
    __syncthreads();
    if (wid == 0) {
        int w = (lane < 8) ? warp_sums[lane] : 0;
#pragma unroll
        for (int o = 1; o < 8; o <<= 1) { int x = __shfl_up_sync(0xFFFFFFFFu, w, o); if (lane >= o) w += x; }
        if (lane < 8) warp_sums[lane] = w;
    }
    __syncthreads();
    int T = warp_sums[7];
    int excl_in_block = ss - s + ((wid > 0) ? warp_sums[wid - 1] : 0);

    if (t == 0) {
        unsigned long long pk = ((unsigned long long)(unsigned)T << 2) | (b == 0 ? 2u : 1u);
        g_state[b] = pk;
        __threadfence();
    }
    if (wid == 0) {
        int running = 0;
        if (b > 0) {
            int look = b - 1 - lane;
            while (true) {
                unsigned long long sv = (look >= 0) ? g_state[look] : 2ULL;
                unsigned flag = (unsigned)(sv & 3ULL);
                int val = (int)(sv >> 2);
                unsigned inv = __ballot_sync(0xFFFFFFFFu, flag == 0u);
                if (inv) continue;
                unsigned pref = __ballot_sync(0xFFFFFFFFu, flag == 2u);
                if (pref) {
                    int fp = __ffs(pref) - 1;
                    int contrib = (lane <= fp) ? val : 0;
#pragma unroll
                    for (int o = 16; o > 0; o >>= 1) contrib += __shfl_xor_sync(0xFFFFFFFFu, contrib, o);
                    running += contrib;
                    break;
                } else {
                    int contrib = val;
#pragma unroll
                    for (int o = 16; o > 0; o >>= 1) contrib += __shfl_xor_sync(0xFFFFFFFFu, contrib, o);
                    running += contrib;
                    look -= 32;
                }
            }
        }
        if (t == 0) {
            s_prefix = running;
            if (b > 0) {
                unsigned long long pk = ((unsigned long long)(unsigned)(running + T) << 2) | 2u;
                g_state[b] = pk;
                __threadfence();
            }
        }
    }
    __syncthreads();

    int run = s_prefix + excl_in_block;
#pragma unroll
    for (int i = 0; i < 4; i++) {
        int idx = idx0 + i;
        if (idx < n) {
            g_rowptr[idx] = run;
            g_cursor[idx] = run;
            int od = g_outdeg[idx]; if (od < 1) od = 1;
            int id = v[i];          if (id < 1) id = 1;
            g_norm_src[idx] = rsqrtf((float)od);
            g_norm_dst[idx] = rsqrtf((float)id);
        }
        run += v[i];
    }
    if (b == 0 && t == 0) g_rowptr[n] = E;
}

// ---------------- kernel 3: scatter + convert, DISJOINT thread ranges (R12 proven) ----------------
__global__ __launch_bounds__(256) void scatter_convert_kernel(
    const int4* __restrict__ src4, const int4* __restrict__ dst4,
    const float4* __restrict__ feat4, int E4, int E, int n, int nconv)
{
    int i = blockIdx.x * 256 + threadIdx.x;
    if (i < E4) {
        int4 s = __ldg(&src4[i]);
        int4 d = __ldg(&dst4[i]);
        g_colidx[atomicAdd(&g_cursor[d.x], 1)] = s.x;
        g_colidx[atomicAdd(&g_cursor[d.y], 1)] = s.y;
        g_colidx[atomicAdd(&g_cursor[d.z], 1)] = s.z;
        g_colidx[atomicAdd(&g_cursor[d.w], 1)] = s.w;
        if (i == 0) {  // tail
            const int* src = (const int*)src4;
            const int* dst = (const int*)dst4;
            for (int e = E4 * 4; e < E; e++) {
                g_colidx[atomicAdd(&g_cursor[dst[e]], 1)] = src[e];
            }
        }
    } else {
        int q = i - E4;                 // uint4 index into g_featbf
        if (q < nconv) {
            int node = q >> 4;          // 16 uint4s per node row
            float ns = __ldg(&g_norm_src[node]);
            float4 f0 = __ldg(&feat4[(size_t)q * 2]);
            float4 f1 = __ldg(&feat4[(size_t)q * 2 + 1]);
            uint4 o;
            o.x = pack_bf16(f0.x * ns, f0.y * ns); o.y = pack_bf16(f0.z * ns, f0.w * ns);
            o.z = pack_bf16(f1.x * ns, f1.y * ns); o.w = pack_bf16(f1.z * ns, f1.w * ns);
            ((uint4*)g_featbf)[q] = o;
        }
    }
    if (i < n) { g_outdeg[i] = 0; g_indeg[i] = 0; }   // consumed by scan; reset for next call
    if (i < 128) g_state[i] = 0ULL;
}

// ---------------- SpMM 128-col, scale-free: out[v] = nd[v] * sum x[u] ----------------
// warp per node, branch-free unroll 4, int4 index loads on aligned body (proven shape)
__global__ __launch_bounds__(256) void spmm128_kernel(
    const uint2* __restrict__ x, uint2* __restrict__ out, int n)
{
    int warp = (blockIdx.x * 256 + threadIdx.x) >> 5;
    int lane = threadIdx.x & 31;
    if (warp >= n) return;
    int beg = __ldg(&g_rowptr[warp]);
    int end = __ldg(&g_rowptr[warp + 1]);
    float dsc = __ldg(&g_norm_dst[warp]);
    const uint2* xp = x + lane;

    unsigned long long a0 = 0ULL, a1 = 0ULL;
    unsigned long long b0 = 0ULL, b1 = 0ULL;
    int e = beg;
    for (; e < end && (e & 3); e++) {
        int u = __ldg(&g_colidx[e]);
        uint2 v = __ldg(xp + (size_t)u * 32);
        acc_bf16x2(b0, v.x); acc_bf16x2(b1, v.y);
    }
    for (; e + 3 < end; e += 4) {
        int4 u = __ldg((const int4*)&g_colidx[e]);
        uint2 v0 = __ldg(xp + (size_t)u.x * 32);
        uint2 v1 = __ldg(xp + (size_t)u.y * 32);
        uint2 v2 = __ldg(xp + (size_t)u.z * 32);
        uint2 v3 = __ldg(xp + (size_t)u.w * 32);
        acc_bf16x2(a0, v0.x); acc_bf16x2(a1, v0.y);
        acc_bf16x2(b0, v1.x); acc_bf16x2(b1, v1.y);
        acc_bf16x2(a0, v2.x); acc_bf16x2(a1, v2.y);
        acc_bf16x2(b0, v3.x); acc_bf16x2(b1, v3.y);
    }
    for (; e < end; e++) {
        int u = __ldg(&g_colidx[e]);
        uint2 v = __ldg(xp + (size_t)u * 32);
        acc_bf16x2(a0, v.x); acc_bf16x2(a1, v.y);
    }
    add_f32x2(a0, b0); add_f32x2(a1, b1);
    float2 f0 = unpack_f32x2(a0);
    float2 f1 = unpack_f32x2(a1);
    uint2 r;
    r.x = pack_bf16(f0.x * dsc, f0.y * dsc);
    r.y = pack_bf16(f1.x * dsc, f1.y * dsc);
    out[(size_t)warp * 32 + lane] = r;
}

// ---------------- SpMM over G (64 cols) fused with +b3 and log_softmax ----------------
__global__ __launch_bounds__(256) void spmm_final_kernel(
    const uint32_t* __restrict__ G, const float* __restrict__ b3,
    float* __restrict__ out, int n)
{
    int warp = (blockIdx.x * 256 + threadIdx.x) >> 5;
    int lane = threadIdx.x & 31;
    if (warp >= n) return;
    int beg = __ldg(&g_rowptr[warp]);
    int end = __ldg(&g_rowptr[warp + 1]);
    float dsc = __ldg(&g_norm_dst[warp]);
    const uint32_t* gp = G + lane;

    unsigned long long a0 = 0ULL, b0 = 0ULL;
    int e = beg;
    for (; e < end && (e & 3); e++) {
        int u = __ldg(&g_colidx[e]);
        acc_bf16x2(b0, __ldg(gp + (size_t)u * 32));
    }
    for (; e + 3 < end; e += 4) {
        int4 u = __ldg((const int4*)&g_colidx[e]);
        uint32_t v0 = __ldg(gp + (size_t)u.x * 32);
        uint32_t v1 = __ldg(gp + (size_t)u.y * 32);
        uint32_t v2 = __ldg(gp + (size_t)u.z * 32);
        uint32_t v3 = __ldg(gp + (size_t)u.w * 32);
        acc_bf16x2(a0, v0); acc_bf16x2(b0, v1);
        acc_bf16x2(a0, v2); acc_bf16x2(b0, v3);
    }
    for (; e < end; e++) {
        int u = __ldg(&g_colidx[e]);
        acc_bf16x2(a0, __ldg(gp + (size_t)u * 32));
    }
    add_f32x2(a0, b0);
    float2 f = unpack_f32x2(a0);
    float2 bb = __ldg(&((const float2*)b3)[lane]);
    float r0 = f.x * dsc + bb.x;
    float r1 = f.y * dsc + bb.y;
    float mx = fmaxf(r0, r1);
#pragma unroll
    for (int o = 16; o > 0; o >>= 1) mx = fmaxf(mx, __shfl_xor_sync(0xFFFFFFFFu, mx, o));
    float es = __expf(r0 - mx) + __expf(r1 - mx);
#pragma unroll
    for (int o = 16; o > 0; o >>= 1) es += __shfl_xor_sync(0xFFFFFFFFu, es, o);
    float lse = logf(es) + mx;
    ((float2*)out)[(size_t)warp * 32 + lane] = make_float2(r0 - lse, r1 - lse);
}

// ---------------- bf16 tensor-core GEMM pieces (512 threads, 16 warps, 32x32 per warp) ----------------
#define AS_STRIDE 68
#define BSS128 136
#define W3S_STRIDE 72
__device__ __forceinline__ void mma_bf16(float* d, const uint32_t* a, const uint32_t* b) {
    asm volatile(
        "mma.sync.aligned.m16n8k16.row.col.f32.bf16.bf16.f32 "
        "{%0,%1,%2,%3}, {%4,%5,%6,%7}, {%8,%9}, {%0,%1,%2,%3};\n"
        : "+f"(d[0]), "+f"(d[1]), "+f"(d[2]), "+f"(d[3])
        : "r"(a[0]), "r"(a[1]), "r"(a[2]), "r"(a[3]), "r"(b[0]), "r"(b[1]));
}

// ---- layer-1 GEMM: C = relu(A@W1 + b1) * rowscale, bf16 out (BN=128) ----
// 512 threads: wm = wid&3 (4 row groups x 32), wn = wid>>2 (4 col groups x 32), acc 32 regs
__global__ __launch_bounds__(512, 2) void gemm_l1_kernel(
    const uint32_t* __restrict__ A, const float* __restrict__ W,
    const float* __restrict__ bias, const float* __restrict__ rowscale,
    uint32_t* __restrict__ C, int M)
{
    extern __shared__ uint32_t smem_u[];
    uint32_t* As = smem_u;                    // [128][68]
    uint32_t* Bs = smem_u + 128 * AS_STRIDE;  // [64][136]

    const int t    = threadIdx.x;
    const int lane = t & 31;
    const int wid  = t >> 5;
    const int m0   = blockIdx.x * 128;
    const int g    = lane >> 2;
    const int tt   = lane & 3;
    const int wm   = wid & 3;
    const int wn   = wid >> 2;

    for (int i = t; i < 64 * 32; i += 512) {
        int kk = i >> 5;
        int n4 = (i & 31) * 4;
        float4 r0 = __ldg((const float4*)&W[(size_t)(2 * kk) * 128 + n4]);
        float4 r1 = __ldg((const float4*)&W[(size_t)(2 * kk + 1) * 128 + n4]);
        uint4 o;
        o.x = pack_bf16(r0.x, r1.x); o.y = pack_bf16(r0.y, r1.y);
        o.z = pack_bf16(r0.z, r1.z); o.w = pack_bf16(r0.w, r1.w);
        *(uint4*)&Bs[kk * BSS128 + n4] = o;
    }
    for (int i = t; i < 128 * 16; i += 512) {
        int r = i >> 4;
        int q = i & 15;
        int gm = m0 + r;
        uint4 v = make_uint4(0u, 0u, 0u, 0u);
        if (gm < M) v = __ldg(&((const uint4*)A)[(size_t)gm * 16 + q]);
        *(uint4*)&As[r * AS_STRIDE + q * 4] = v;
    }
    __syncthreads();

    float acc[2][4][4];
#pragma unroll
    for (int i = 0; i < 2; i++)
#pragma unroll
        for (int j = 0; j < 4; j++)
#pragma unroll
            for (int c = 0; c < 4; c++) acc[i][j][c] = 0.f;

#pragma unroll
    for (int ks = 0; ks < 8; ks++) {
        int kb = ks * 8;
        uint32_t bf[4][2];
#pragma unroll
        for (int j = 0; j < 4; j++) {
            int n = wn * 32 + j * 8 + g;
            bf[j][0] = Bs[(kb + tt) * BSS128 + n];
            bf[j][1] = Bs[(kb + tt + 4) * BSS128 + n];
        }
#pragma unroll
        for (int i = 0; i < 2; i++) {
            int m = wm * 32 + i * 16;
            uint32_t af[4];
            af[0] = As[(m + g)     * AS_STRIDE + kb + tt];
            af[1] = As[(m + g + 8) * AS_STRIDE + kb + tt];
            af[2] = As[(m + g)     * AS_STRIDE + kb + tt + 4];
            af[3] = As[(m + g + 8) * AS_STRIDE + kb + tt + 4];
#pragma unroll
            for (int j = 0; j < 4; j++) mma_bf16(acc[i][j], af, bf[j]);
        }
    }

#pragma unroll
    for (int i = 0; i < 2; i++) {
        int m_lo = m0 + wm * 32 + i * 16 + g;
        int m_hi = m_lo + 8;
        float rs_lo = 1.f, rs_hi = 1.f;
        if (m_lo < M) rs_lo = __ldg(&rowscale[m_lo]);
        if (m_hi < M) rs_hi = __ldg(&rowscale[m_hi]);
#pragma unroll
        for (int j = 0; j < 4; j++) {
            int n = wn * 32 + j * 8 + 2 * tt;
            float b0 = __ldg(&bias[n]), b1 = __ldg(&bias[n + 1]);
            float v0 = fmaxf(acc[i][j][0] + b0, 0.f) * rs_lo;
            float v1 = fmaxf(acc[i][j][1] + b1, 0.f) * rs_lo;
            float v2 = fmaxf(acc[i][j][2] + b0, 0.f) * rs_hi;
            float v3 = fmaxf(acc[i][j][3] + b1, 0.f) * rs_hi;
            if (m_lo < M) C[(size_t)m_lo * 64 + (n >> 1)] = pack_bf16(v0, v1);
            if (m_hi < M) C[(size_t)m_hi * 64 + (n >> 1)] = pack_bf16(v2, v3);
        }
    }
}

// ---- fused layers 2+3 GEMM: g = (relu(A@W2 + b2) * ns) @ W3, bf16 out (64 cols) ----
// 512 threads; mainloop2 uses 4 col groups x 16 cols (NT2=2)
__global__ __launch_bounds__(512, 2) void gemm_fused_kernel(
    const uint32_t* __restrict__ A,   // m2 bf16 pairs, row stride 64
    const float* __restrict__ W2,     // [128][128] fp32
    const float* __restrict__ bias,   // b2
    const float* __restrict__ rowscale,
    const float* __restrict__ W3,     // [128][64] fp32
    uint32_t* __restrict__ C,         // g bf16 pairs, row stride 32
    int M)
{
    extern __shared__ uint32_t smem_u[];
    uint32_t* As  = smem_u;                           // [128][68]  (m2, then h2)
    uint32_t* Bs  = smem_u + 128 * AS_STRIDE;         // [64][136]  (W2)
    uint32_t* W3s = Bs + 64 * BSS128;                 // [64][72]   (W3)

    const int t    = threadIdx.x;
    const int lane = t & 31;
    const int wid  = t >> 5;
    const int m0   = blockIdx.x * 128;
    const int g    = lane >> 2;
    const int tt   = lane & 3;
    const int wm   = wid & 3;
    const int wn   = wid >> 2;

    for (int i = t; i < 64 * 32; i += 512) {
        int kk = i >> 5;
        int n4 = (i & 31) * 4;
        float4 r0 = __ldg((const float4*)&W2[(size_t)(2 * kk) * 128 + n4]);
        float4 r1 = __ldg((const float4*)&W2[(size_t)(2 * kk + 1) * 128 + n4]);
        uint4 o;
        o.x = pack_bf16(r0.x, r1.x); o.y = pack_bf16(r0.y, r1.y);
        o.z = pack_bf16(r0.z, r1.z); o.w = pack_bf16(r0.w, r1.w);
        *(uint4*)&Bs[kk * BSS128 + n4] = o;
    }
    for (int i = t; i < 64 * 16; i += 512) {
        int kk = i >> 4;
        int n4 = (i & 15) * 4;
        float4 r0 = __ldg((const float4*)&W3[(size_t)(2 * kk) * 64 + n4]);
        float4 r1 = __ldg((const float4*)&W3[(size_t)(2 * kk + 1) * 64 + n4]);
        uint4 o;
        o.x = pack_bf16(r0.x, r1.x); o.y = pack_bf16(r0.y, r1.y);
        o.z = pack_bf16(r0.z, r1.z); o.w = pack_bf16(r0.w, r1.w);
        *(uint4*)&W3s[kk * W3S_STRIDE + n4] = o;
    }
    for (int i = t; i < 128 * 16; i += 512) {
        int r = i >> 4;
        int q = i & 15;
        int gm = m0 + r;
        uint4 v = make_uint4(0u, 0u, 0u, 0u);
        if (gm < M) v = __ldg(&((const uint4*)A)[(size_t)gm * 16 + q]);
        *(uint4*)&As[r * AS_STRIDE + q * 4] = v;
    }
    __syncthreads();

    // ---- mainloop 1: acc = m2 @ W2 (32x32 per warp) ----
    float acc[2][4][4];
#pragma unroll
    for (int i = 0; i < 2; i++)
#pragma unroll
        for (int j = 0; j < 4; j++)
#pragma unroll
            for (int c = 0; c < 4; c++) acc[i][j][c] = 0.f;

#pragma unroll
    for (int ks = 0; ks < 8; ks++) {
        int kb = ks * 8;
        uint32_t bf[4][2];
#pragma unroll
        for (int j = 0; j < 4; j++) {
            int n = wn * 32 + j * 8 + g;
            bf[j][0] = Bs[(kb + tt) * BSS128 + n];
            bf[j][1] = Bs[(kb + tt + 4) * BSS128 + n];
        }
#pragma unroll
        for (int i = 0; i < 2; i++) {
            int m = wm * 32 + i * 16;
            uint32_t af[4];
            af[0] = As[(m + g)     * AS_STRIDE + kb + tt];
            af[1] = As[(m + g + 8) * AS_STRIDE + kb + tt];
            af[2] = As[(m + g)     * AS_STRIDE + kb + tt + 4];
            af[3] = As[(m + g + 8) * AS_STRIDE + kb + tt + 4];
#pragma unroll
            for (int j = 0; j < 4; j++) mma_bf16(acc[i][j], af, bf[j]);
        }
    }
    __syncthreads();   // all warps done reading As (m2) before overwriting with h2

    // ---- epilogue 1: h2 = relu(acc + b2) * ns  ->  As smem ----
#pragma unroll
    for (int i = 0; i < 2; i++) {
        int row_lo = wm * 32 + i * 16 + g;
        int m_lo = m0 + row_lo;
        int m_hi = m_lo + 8;
        float rs_lo = 1.f, rs_hi = 1.f;
        if (m_lo < M) rs_lo = __ldg(&rowscale[m_lo]);
        if (m_hi < M) rs_hi = __ldg(&rowscale[m_hi]);
#pragma unroll
        for (int j = 0; j < 4; j++) {
            int n = wn * 32 + j * 8 + 2 * tt;
            float b0 = __ldg(&bias[n]), b1 = __ldg(&bias[n + 1]);
            float v0 = fmaxf(acc[i][j][0] + b0, 0.f) * rs_lo;
            float v1 = fmaxf(acc[i][j][1] + b1, 0.f) * rs_lo;
            float v2 = fmaxf(acc[i][j][2] + b0, 0.f) * rs_hi;
            float v3 = fmaxf(acc[i][j][3] + b1, 0.f) * rs_hi;
            int colp = n >> 1;
            As[row_lo * AS_STRIDE + colp]       = pack_bf16(v0, v1);
            As[(row_lo + 8) * AS_STRIDE + colp] = pack_bf16(v2, v3);
        }
    }
    __syncthreads();

    // ---- mainloop 2: acc2 = h2 @ W3 (32 rows x 16 cols per warp) ----
    float acc2[2][2][4];
#pragma unroll
    for (int i = 0; i < 2; i++)
#pragma unroll
        for (int j = 0; j < 2; j++)
#pragma unroll
            for (int c = 0; c < 4; c++) acc2[i][j][c] = 0.f;

#pragma unroll
    for (int ks = 0; ks < 8; ks++) {
        int kb = ks * 8;
        uint32_t bf[2][2];
#pragma unroll
        for (int j = 0; j < 2; j++) {
            int n = wn * 16 + j * 8 + g;
            bf[j][0] = W3s[(kb + tt) * W3S_STRIDE + n];
            bf[j][1] = W3s[(kb + tt + 4) * W3S_STRIDE + n];
        }
#pragma unroll
        for (int i = 0; i < 2; i++) {
            int m = wm * 32 + i * 16;
            uint32_t af[4];
            af[0] = As[(m + g)     * AS_STRIDE + kb + tt];
            af[1] = As[(m + g + 8) * AS_STRIDE + kb + tt];
            af[2] = As[(m + g)     * AS_STRIDE + kb + tt + 4];
            af[3] = As[(m + g + 8) * AS_STRIDE + kb + tt + 4];
#pragma unroll
            for (int j = 0; j < 2; j++) mma_bf16(acc2[i][j], af, bf[j]);
        }
    }

#pragma unroll
    for (int i = 0; i < 2; i++) {
        int m_lo = m0 + wm * 32 + i * 16 + g;
        int m_hi = m_lo + 8;
#pragma unroll
        for (int j = 0; j < 2; j++) {
            int n = wn * 16 + j * 8 + 2 * tt;
            if (m_lo < M) C[(size_t)m_lo * 32 + (n >> 1)] = pack_bf16(acc2[i][j][0], acc2[i][j][1]);
            if (m_hi < M) C[(size_t)m_hi * 32 + (n >> 1)] = pack_bf16(acc2[i][j][2], acc2[i][j][3]);
        }
    }
}

#define GEMM_L1_SMEM    ((128 * AS_STRIDE + 64 * BSS128) * 4)
#define GEMM_FUSED_SMEM ((128 * AS_STRIDE + 64 * BSS128 + 64 * W3S_STRIDE) * 4)

// ---------------- launch ----------------
extern "C" void kernel_launch(void* const* d_in, const int* in_sizes, int n_in,
                              void* d_out, int out_size)
{
    const float* features = (const float*)d_in[0];
    const int*   src      = (const int*)  d_in[1];
    const int*   dst      = (const int*)  d_in[2];
    const float* W1       = (const float*)d_in[3];
    const float* b1       = (const float*)d_in[4];
    const float* W2       = (const float*)d_in[5];
    const float* b2       = (const float*)d_in[6];
    const float* W3       = (const float*)d_in[7];
    const float* b3       = (const float*)d_in[8];
    float* out = (float*)d_out;

    const int N = in_sizes[0] / DIN;   // 100000
    const int E = in_sizes[1];         // 1600000

    uint32_t* featbf; cudaGetSymbolAddress((void**)&featbf, g_featbf);
    uint32_t* aggA;   cudaGetSymbolAddress((void**)&aggA,   g_aggA);
    uint32_t* hbuf;   cudaGetSymbolAddress((void**)&hbuf,   g_h);
    uint32_t* Gbuf;   cudaGetSymbolAddress((void**)&Gbuf,   g_G);
    float*    nsrc;   cudaGetSymbolAddress((void**)&nsrc,   g_norm_src);

    static bool attr_done = false;
    if (!attr_done) {
        cudaFuncSetAttribute((const void*)gemm_l1_kernel,
                             cudaFuncAttributeMaxDynamicSharedMemorySize, GEMM_L1_SMEM);
        cudaFuncSetAttribute((const void*)gemm_fused_kernel,
                             cudaFuncAttributeMaxDynamicSharedMemorySize, GEMM_FUSED_SMEM);
        attr_done = true;
    }

    const int E4 = E >> 2;
    const int nconv = N * 16;                       // one uint4 per convert thread
    const int sc_threads = E4 + nconv;              // disjoint ranges: scatter | convert
    const int scan_blocks = (N + 1023) / 1024;      // 98 < 148 SMs (lookback safety)
    const int spmm_blocks = (N * 32 + 255) / 256;   // warp per node
    const int gemm_blocks = (N + 127) / 128;

    // ---- CSR build ----
    deg_kernel<<<(E4 + 255) / 256, 256>>>((const int4*)src, (const int4*)dst, E4, E);
    scan_kernel<<<scan_blocks, 256>>>(N, E);
    scatter_convert_kernel<<<(sc_threads + 255) / 256, 256>>>(
        (const int4*)src, (const int4*)dst, (const float4*)features, E4, E, N, nconv);

    // ---- layer 1 ----
    spmm128_kernel<<<spmm_blocks, 256>>>((const uint2*)featbf, (uint2*)aggA, N);
    gemm_l1_kernel<<<gemm_blocks, 512, GEMM_L1_SMEM>>>(aggA, W1, b1, nsrc, hbuf, N);

    // ---- layer 2 aggregate, then fused (layer-2 linear + layer-3 linear) ----
    spmm128_kernel<<<spmm_blocks, 256>>>((const uint2*)hbuf, (uint2*)aggA, N);
    gemm_fused_kernel<<<gemm_blocks, 512, GEMM_FUSED_SMEM>>>(aggA, W2, b2, nsrc, W3, Gbuf, N);

    // ---- layer 3 aggregate + b3 + log_softmax ----
    spmm_final_kernel<<<spmm_blocks, 256>>>(Gbuf, b3, out, N);
}